// round 17
// baseline (speedup 1.0000x reference)
#include <cuda_runtime.h>
#include <math.h>
#include <stdint.h>

#define NROWS 100000
#define DIMS  1443
#define NB    148
#define NT    256
#define NWARP 8
#define GSTRIDE (NB*NT)
#define WPG   (37*NWARP)        // 296 warps per alignment phase
#define JROWS 25000             // rows per phase: row = p + 4*jj
#define SCAP  1024
#define RSTAGE 2
#define ROWF  1440
#define ROWB  5760
#define STAGE_BYTES (NWARP*RSTAGE*ROWB)   // 92160
#define DSMEM STAGE_BYTES
#define ACCW  1444

// ---------------- device scratch (allocation-free) ----------------
__device__ unsigned g_bar = 0;
__device__ float    g_y1[NROWS], g_y2[NROWS], g_y3[NROWS];
__device__ float    g_prod[NROWS];
__device__ float    g_coef[NROWS];
__device__ unsigned g_key[NROWS];
__device__ unsigned g_hist[3][65536];     // zeroed in C4 of its round (replay invariant)
__device__ unsigned g_hist8[3][256];
__device__ unsigned g_candk[NROWS];
__device__ int      g_candr[NROWS];
__device__ int      g_ncand3[3];
__device__ float    g_fpart[NB][DIMS];

__device__ __forceinline__ unsigned f2key(float f) {
    unsigned u = __float_as_uint(f);
    return (u & 0x80000000u) ? ~u : (u | 0x80000000u);
}
__device__ __forceinline__ uint32_t s2u(const void* p) {
    uint32_t a;
    asm("{ .reg .u64 t; cvta.to.shared.u64 t, %1; cvt.u32.u64 %0, t; }"
        : "=r"(a) : "l"(p));
    return a;
}
__device__ __forceinline__ void mb_init(uint32_t m, uint32_t c) {
    asm volatile("mbarrier.init.shared.b64 [%0], %1;" :: "r"(m), "r"(c) : "memory");
}
__device__ __forceinline__ void mb_extx(uint32_t m, uint32_t b) {
    asm volatile("mbarrier.arrive.expect_tx.shared.b64 _, [%0], %1;"
                 :: "r"(m), "r"(b) : "memory");
}
__device__ __forceinline__ void bulk_g2s(uint32_t dst, const void* src,
                                         uint32_t bytes, uint32_t m) {
    asm volatile("cp.async.bulk.shared::cta.global.mbarrier::complete_tx::bytes "
                 "[%0], [%1], %2, [%3];"
                 :: "r"(dst), "l"(src), "r"(bytes), "r"(m) : "memory");
}
__device__ __forceinline__ void mb_wait(uint32_t m, uint32_t par) {
    uint32_t done;
    asm volatile(
        "{ .reg .pred p; mbarrier.try_wait.parity.acquire.cta.shared::cta.b64 "
        "p, [%1], %2; selp.b32 %0,1,0,p; }"
        : "=r"(done) : "r"(m), "r"(par) : "memory");
    while (!done) {
        asm volatile(
            "{ .reg .pred p; mbarrier.try_wait.parity.acquire.cta.shared::cta.b64 "
            "p, [%1], %2, 0x989680; selp.b32 %0,1,0,p; }"
            : "=r"(done) : "r"(m), "r"(par) : "memory");
    }
}
__device__ __forceinline__ void fence_async() {
    asm volatile("fence.proxy.async.shared::cta;" ::: "memory");
}

// grid barrier: arrive via atomicAdd, spin on plain volatile load
__device__ __forceinline__ void gbar(unsigned ph) {
    __syncthreads();
    if (threadIdx.x == 0) {
        __threadfence();
        atomicAdd(&g_bar, 1u);
        const unsigned tgt = ph * NB;
        while (*(volatile unsigned*)&g_bar < tgt) __nanosleep(64);
        __threadfence();
    }
    __syncthreads();
}

__device__ __forceinline__ unsigned upd(int r, int i, bool sel,
                                        float i1, float i2, float i3) {
    if (r == 0) {
        if (sel) {
            float s = tanhf(__ldcg(&g_y1[i]) * i1);
            g_prod[i] = s;
            unsigned nk = f2key(s * __ldcg(&g_y2[i]));
            g_key[i] = nk;
            return nk;
        }
        g_key[i] = 0u; return 0u;
    } else if (r == 1) {
        if (sel) {
            float p = __ldcg(&g_prod[i]);
            float s = tanhf(p * __ldcg(&g_y2[i]) * i2);
            p *= s;
            g_prod[i] = p;
            unsigned nk = f2key(p * __ldcg(&g_y3[i]));
            g_key[i] = nk;
            return nk;
        }
        g_key[i] = 0u; return 0u;
    } else {
        float cf = 0.f;
        if (sel) {
            float p = __ldcg(&g_prod[i]);
            float s = tanhf(p * __ldcg(&g_y3[i]) * i3);
            cf = p * s * (1.0f / 12500.0f);
        }
        g_coef[i] = cf;
        return 0u;
    }
}

extern __shared__ float stg[];   // [8 warps][2 slots][1440 floats]

__global__ void __launch_bounds__(NT, 1) k_persist(
    const float* __restrict__ x,
    const float* __restrict__ w1, const float* __restrict__ w2,
    const float* __restrict__ w3, float* __restrict__ out)
{
    const int tid  = threadIdx.x, bid = blockIdx.x;
    const int lane = tid & 31,    wid = tid >> 5;
    const int gtid = bid * NT + tid;
    const int p    = bid & 3;                  // alignment phase of this block
    const int wg   = (bid >> 2) * NWARP + wid; // warp id within phase [0,296)

    __shared__ float    s_n[3][NWARP];
    __shared__ float    s_inv[3];
    __shared__ unsigned s_scan[256];
    __shared__ unsigned s_ck[SCAP];
    __shared__ int      s_cr[SCAP];
    __shared__ unsigned s_Bsel;
    __shared__ int      s_needB;
    __shared__ int      s_cb, s_nr;
    __shared__ __align__(8) uint64_t s_mb[NWARP][RSTAGE];

    // ---- w norms ----
    {
        float a0 = 0.f, a1 = 0.f, a2 = 0.f;
        for (int i = tid; i < DIMS; i += NT) {
            float v1 = __ldg(w1 + i), v2 = __ldg(w2 + i), v3 = __ldg(w3 + i);
            a0 += v1 * v1; a1 += v2 * v2; a2 += v3 * v3;
        }
#pragma unroll
        for (int off = 16; off > 0; off >>= 1) {
            a0 += __shfl_down_sync(0xffffffffu, a0, off);
            a1 += __shfl_down_sync(0xffffffffu, a1, off);
            a2 += __shfl_down_sync(0xffffffffu, a2, off);
        }
        if (lane == 0) { s_n[0][wid] = a0; s_n[1][wid] = a1; s_n[2][wid] = a2; }
    }
    if (tid < NWARP * RSTAGE) {
        mb_init(s2u(&s_mb[tid >> 1][tid & 1]), 1);
        fence_async();
    }
    if (bid == 0 && tid < 3) g_ncand3[tid] = 0;
    __syncthreads();
    if (tid < 3) {
        float s = 0.f;
        for (int w = 0; w < NWARP; w++) s += s_n[tid][w];
        s_inv[tid] = 1.0f / sqrtf(s);
    }
    __syncthreads();
    const float i1 = s_inv[0], i2 = s_inv[1], i3 = s_inv[2];

    // ---------------- phase B: GEMV, w in REGISTERS, TMA bulk ring ----------------
    {
        // per-lane w slices (fixed for the whole GEMV)
        float4 wa[12], wb[12], wc[12];
#pragma unroll
        for (int k = 0; k < 12; k++) {
            int m = lane + 32 * k;
            if (m < 360) {
                int col = p + 4 * m;
                wa[k] = make_float4(__ldg(w1+col), __ldg(w1+col+1), __ldg(w1+col+2), __ldg(w1+col+3));
                wb[k] = make_float4(__ldg(w2+col), __ldg(w2+col+1), __ldg(w2+col+2), __ldg(w2+col+3));
                wc[k] = make_float4(__ldg(w3+col), __ldg(w3+col+1), __ldg(w3+col+2), __ldg(w3+col+3));
            } else {
                wa[k] = make_float4(0.f, 0.f, 0.f, 0.f);
                wb[k] = wa[k]; wc[k] = wa[k];
            }
        }
        const int m11 = (lane < 8) ? (352 + lane) : 359;   // safe smem index for k=11
        const int e = lane - 8;
        const bool haveE = (e >= 0 && e < 3);
        int ecol = 0; float we1 = 0.f, we2 = 0.f, we3 = 0.f;
        if (haveE) {
            ecol = (e < p) ? e : p + 1440 + (e - p);
            we1 = __ldg(w1 + ecol); we2 = __ldg(w2 + ecol); we3 = __ldg(w3 + ecol);
        }
        const uint32_t stB = s2u(stg) + (uint32_t)(wid * RSTAGE) * ROWB;
        const uint32_t mbA[2] = { s2u(&s_mb[wid][0]), s2u(&s_mb[wid][1]) };

        auto issueRow = [&](int jj, int slot) {
            if (jj < JROWS && lane == 0) {
                int row = p + 4 * jj;
                mb_extx(mbA[slot], ROWB);
                bulk_g2s(stB + (uint32_t)slot * ROWB,
                         x + (size_t)row * DIMS + p, ROWB, mbA[slot]);
            }
        };
        issueRow(wg, 0);
        issueRow(wg + WPG, 1);

        int phs0 = 0, phs1 = 0, t = 0;
        for (int jj = wg; jj < JROWS; jj += WPG, ++t) {
            const int slot = t & 1;
            const int row = p + 4 * jj;
            float xe = haveE ? __ldcg(x + (size_t)row * DIMS + ecol) : 0.f;
            if (slot == 0) { mb_wait(mbA[0], phs0); phs0 ^= 1; }
            else           { mb_wait(mbA[1], phs1); phs1 ^= 1; }
            const float4* rb = (const float4*)(stg + (wid * RSTAGE + slot) * ROWF);
            float4 A0 = make_float4(0.f,0.f,0.f,0.f);
            float4 A1 = A0, A2 = A0;
#pragma unroll
            for (int k = 0; k < 12; k++) {
                const int m = (k < 11) ? (lane + 32 * k) : m11;
                float4 v = rb[m];
                A0.x += v.x*wa[k].x; A0.y += v.y*wa[k].y;
                A0.z += v.z*wa[k].z; A0.w += v.w*wa[k].w;
                A1.x += v.x*wb[k].x; A1.y += v.y*wb[k].y;
                A1.z += v.z*wb[k].z; A1.w += v.w*wb[k].w;
                A2.x += v.x*wc[k].x; A2.y += v.y*wc[k].y;
                A2.z += v.z*wc[k].z; A2.w += v.w*wc[k].w;
            }
            float a0 = (A0.x + A0.y) + (A0.z + A0.w);
            float a1 = (A1.x + A1.y) + (A1.z + A1.w);
            float a2 = (A2.x + A2.y) + (A2.z + A2.w);
            if (haveE) { a0 += xe * we1; a1 += xe * we2; a2 += xe * we3; }
            fence_async();                // order smem reads before async reuse
            __syncwarp();
            issueRow(jj + 2 * WPG, slot); // refill slot
#pragma unroll
            for (int off = 16; off > 0; off >>= 1) {
                a0 += __shfl_down_sync(0xffffffffu, a0, off);
                a1 += __shfl_down_sync(0xffffffffu, a1, off);
                a2 += __shfl_down_sync(0xffffffffu, a2, off);
            }
            if (lane == 0) {
                g_y1[row] = a0; g_y2[row] = a1; g_y3[row] = a2;
                unsigned key = f2key(a0);
                g_key[row] = key;
                atomicAdd(&g_hist[0][key >> 16], 1u);
                atomicAdd(&g_hist8[0][key >> 24], 1u);
            }
        }
    }
    unsigned ph = 0;
    gbar(++ph);

    // ---------------- selection rounds (2 barriers each) ----------------
    for (int r = 0; r < 3; r++) {
        const int need = (r == 0) ? 50000 : ((r == 1) ? 25000 : 12500);
        unsigned* hist = g_hist[r];

        // C2: two-level scan in EVERY block (512 bin reads total)
        {
            unsigned own = __ldcg(&g_hist8[r][255 - tid]);
            s_scan[tid] = own;
            __syncthreads();
#pragma unroll
            for (int off = 1; off < 256; off <<= 1) {
                unsigned v = (tid >= off) ? s_scan[tid - off] : 0u;
                __syncthreads();
                s_scan[tid] += v;
                __syncthreads();
            }
            {
                unsigned incl = s_scan[tid], excl = incl - own;
                if ((int)excl < need && need <= (int)incl) {
                    s_cb = 255 - tid;
                    s_nr = need - (int)excl;
                }
            }
            __syncthreads();
            const int cb = s_cb, nr = s_nr;
            unsigned own2 = __ldcg(&hist[cb * 256 + 255 - tid]);
            s_scan[tid] = own2;
            __syncthreads();
#pragma unroll
            for (int off = 1; off < 256; off <<= 1) {
                unsigned v = (tid >= off) ? s_scan[tid - off] : 0u;
                __syncthreads();
                s_scan[tid] += v;
                __syncthreads();
            }
            {
                unsigned incl = s_scan[tid], excl = incl - own2;
                if ((int)excl < nr && nr <= (int)incl) {
                    s_Bsel = (unsigned)(cb * 256 + 255 - tid);
                    s_needB = nr - (int)excl;
                }
            }
            __syncthreads();
        }

        // C3: classify + next-round hists + boundary candidates
        {
            const unsigned Bv = s_Bsel;
            for (int i = gtid; i < NROWS; i += GSTRIDE) {
                unsigned key = __ldcg(&g_key[i]);
                if (key) {
                    unsigned b = key >> 16;
                    if (b > Bv) {
                        unsigned nk = upd(r, i, true, i1, i2, i3);
                        if (r < 2) {
                            atomicAdd(&g_hist[r + 1][nk >> 16], 1u);
                            atomicAdd(&g_hist8[r + 1][nk >> 24], 1u);
                        }
                    } else if (b == Bv) {
                        int ci = atomicAdd(&g_ncand3[r], 1);
                        g_candk[ci] = key; g_candr[ci] = i;
                    } else {
                        upd(r, i, false, i1, i2, i3);
                    }
                } else {
                    upd(r, i, false, i1, i2, i3);   // writes coef=0 when r==2
                }
            }
        }
        gbar(++ph);

        // C4: rank boundary candidates; re-zero hists (replay invariant)
        {
            for (int i = gtid; i < 65536; i += GSTRIDE) hist[i] = 0u;
            if (bid == 0) g_hist8[r][tid] = 0u;
            int m  = __ldcg(&g_ncand3[r]);
            int nB = s_needB;
            int mc = (m < SCAP) ? m : SCAP;
            for (int j = tid; j < mc; j += NT) {
                s_ck[j] = __ldcg(&g_candk[j]);
                s_cr[j] = __ldcg(&g_candr[j]);
            }
            __syncthreads();
            for (int ci = gtid; ci < m; ci += GSTRIDE) {
                unsigned mk = (ci < mc) ? s_ck[ci] : __ldcg(&g_candk[ci]);
                int      mr = (ci < mc) ? s_cr[ci] : __ldcg(&g_candr[ci]);
                int cnt = 0;
                for (int j = 0; j < mc; j++) {
                    unsigned kj = s_ck[j]; int rj = s_cr[j];
                    cnt += (kj > mk || (kj == mk && rj < mr)) ? 1 : 0;
                }
                for (int j = mc; j < m; j++) {
                    unsigned kj = __ldcg(&g_candk[j]); int rj = __ldcg(&g_candr[j]);
                    cnt += (kj > mk || (kj == mk && rj < mr)) ? 1 : 0;
                }
                bool sel = (cnt < nB);
                unsigned nk = upd(r, mr, sel, i1, i2, i3);
                if (r < 2 && sel) {
                    atomicAdd(&g_hist[r + 1][nk >> 16], 1u);
                    atomicAdd(&g_hist8[r + 1][nk >> 24], 1u);
                }
            }
            __syncthreads();
        }
        gbar(++ph);
    }

    // ---------------- phase D: gather + block smem reduction ----------------
    {
        const int e = lane - 8;
        const bool haveE = (e >= 0 && e < 3);
        const int ecol = haveE ? ((e < p) ? e : p + 1440 + (e - p)) : 0;
        const int m11 = 352 + lane;
        const bool l8 = (lane < 8);
        float4 acc[12];
#pragma unroll
        for (int kk = 0; kk < 12; kk++) acc[kk] = make_float4(0.f, 0.f, 0.f, 0.f);
        float accE = 0.f;
        for (int jj = wg; jj < JROWS; jj += WPG) {
            int row = p + 4 * jj;
            float c = __ldcg(&g_coef[row]);
            if (c == 0.0f) continue;
            const float4* px = (const float4*)(x + (size_t)row * DIMS + p);
#pragma unroll
            for (int k = 0; k < 11; k++) {
                float4 v = __ldg(px + lane + 32 * k);
                acc[k].x += c * v.x; acc[k].y += c * v.y;
                acc[k].z += c * v.z; acc[k].w += c * v.w;
            }
            if (l8) {
                float4 v = __ldg(px + m11);
                acc[11].x += c * v.x; acc[11].y += c * v.y;
                acc[11].z += c * v.z; acc[11].w += c * v.w;
            }
            if (haveE) accE += c * __ldg(x + (size_t)row * DIMS + ecol);
        }
        float* sa = stg + wid * ACCW;   // stage area is free now
#pragma unroll
        for (int k = 0; k < 12; k++) {
            if (k < 11 || l8) {
                int m = (k < 11) ? (lane + 32 * k) : m11;
                int cb = p + 4 * m;
                sa[cb] = acc[k].x; sa[cb + 1] = acc[k].y;
                sa[cb + 2] = acc[k].z; sa[cb + 3] = acc[k].w;
            }
        }
        if (haveE) sa[ecol] = accE;
        __syncthreads();
        for (int col = tid; col < DIMS; col += NT) {
            float s = 0.f;
#pragma unroll
            for (int w = 0; w < NWARP; w++) s += stg[w * ACCW + col];
            g_fpart[bid][col] = s;
        }
    }
    gbar(++ph);

    // ---------------- E: reduce 148 block partials -> out ----------------
    if (bid * NWARP + wid < 46) {
        int col = (bid * NWARP + wid) * 32 + lane;
        if (col < DIMS) {
            float s = 0.f;
#pragma unroll 8
            for (int j = 0; j < NB; j++) s += __ldcg(&g_fpart[j][col]);
            out[col] = s;
        }
    }

    // ---- final arrive-only barrier; block 0 resets counter ----
    __syncthreads();
    if (tid == 0) {
        __threadfence();
        const unsigned tgt = (ph + 1) * NB;
        atomicAdd(&g_bar, 1u);
        if (bid == 0) {
            while (*(volatile unsigned*)&g_bar < tgt) __nanosleep(64);
            atomicExch(&g_bar, 0u);
            __threadfence();
        }
    }
}

// ---------------- launch ----------------
extern "C" void kernel_launch(void* const* d_in, const int* in_sizes, int n_in,
                              void* d_out, int out_size) {
    const float* x  = (const float*)d_in[0];
    // d_in[1] edge_index, d_in[2] edge_attr: dead inputs
    const float* w1 = (const float*)d_in[3];
    const float* w2 = (const float*)d_in[4];
    const float* w3 = (const float*)d_in[5];
    float* out = (float*)d_out;

    cudaFuncSetAttribute(k_persist, cudaFuncAttributeMaxDynamicSharedMemorySize,
                         DSMEM);
    k_persist<<<NB, NT, DSMEM>>>(x, w1, w2, w3, out);
}